// round 13
// baseline (speedup 1.0000x reference)
#include <cuda_runtime.h>
#include <cuda_fp16.h>
#include <cstdint>
#include <cstddef>

// Problem constants
#define BB 4
#define LL 4096
#define DD 1024
#define MM (BB * LL)      // 16384
#define KK 1024

// Heterogeneous split: tensor cores do rows 0..95, HFMA2 (fma pipe) rows 96..127
#define BM 128
#define BN 128            // per gate
#define BK 64             // k-chunk in halves = 128B per row
#define NKC (KK / BK)     // 16
#define PIPE 3
#define MT_ROWS 96        // tensor M rows per CTA

#define ARR_BYTES 16384                    // 128 rows x 128B
#define STAGE_BYTES (3 * ARR_BYTES)        // 49152
#define SM_BIAS  64
#define SM_STAGE 4096
#define SMEM_TOTAL (SM_STAGE + PIPE * STAGE_BYTES)  // 151552 B

#define SWZ(o) ((o) ^ (((o) >> 3) & 0x70))

#define NYB 128           // m-blocks (128 rows each); 32 per batch
#define YPB 32            // m-blocks per batch

// Scratch (allocation-free rule: __device__ globals)
__device__ __half g_x16 [(size_t)MM * KK];
__device__ __half g_wa16[(size_t)DD * KK];
__device__ __half g_wx16[(size_t)DD * KK];
__device__ float  g_Pc[NYB * DD];
__device__ float  g_Hc[NYB * DD];
__device__ int    g_sync[16 + NYB * 8];  // [0]=ticket, [16+tk]=publish flag

// ---------- helpers ----------
__device__ __forceinline__ uint32_t smem_u32(const void* p) {
    uint32_t a;
    asm("{ .reg .u64 t; cvta.to.shared.u64 t, %1; cvt.u32.u64 %0, t; }" : "=r"(a) : "l"(p));
    return a;
}

__device__ __forceinline__ void cpa16(uint32_t dst, const void* src) {
    asm volatile("cp.async.cg.shared.global [%0], [%1], 16;" :: "r"(dst), "l"(src));
}

__device__ __forceinline__ void ldmx4(uint32_t r[4], uint32_t addr) {
    asm volatile("ldmatrix.sync.aligned.m8n8.x4.shared.b16 {%0,%1,%2,%3}, [%4];"
                 : "=r"(r[0]), "=r"(r[1]), "=r"(r[2]), "=r"(r[3]) : "r"(addr));
}

__device__ __forceinline__ void mma_f16(float c[4], const uint32_t a[4], const uint32_t b[2]) {
    asm volatile(
        "mma.sync.aligned.m16n8k16.row.col.f32.f16.f16.f32 "
        "{%0,%1,%2,%3}, {%4,%5,%6,%7}, {%8,%9}, {%0,%1,%2,%3};"
        : "+f"(c[0]), "+f"(c[1]), "+f"(c[2]), "+f"(c[3])
        : "r"(a[0]), "r"(a[1]), "r"(a[2]), "r"(a[3]), "r"(b[0]), "r"(b[1]));
}

__device__ __forceinline__ void st_release(int* p, int v) {
    asm volatile("st.release.gpu.global.s32 [%0], %1;" :: "l"(p), "r"(v) : "memory");
}
__device__ __forceinline__ int ld_acquire(int* p) {
    int v;
    asm volatile("ld.acquire.gpu.global.s32 %0, [%1];" : "=r"(v) : "l"(p) : "memory");
    return v;
}

// ---------- fp32 -> fp16 pre-convert ----------
__global__ __launch_bounds__(256) void convert_f16(
    const float* __restrict__ x, const float* __restrict__ Wa, const float* __restrict__ Wx)
{
    size_t gid = (size_t)blockIdx.x * 256 + threadIdx.x;
    {
        float4 v = *(const float4*)(x + gid * 4);
        __half2* d = (__half2*)g_x16 + gid * 2;
        d[0] = __floats2half2_rn(v.x, v.y);
        d[1] = __floats2half2_rn(v.z, v.w);
    }
    if (gid < (size_t)(DD * KK) / 4) {
        float4 va = *(const float4*)(Wa + gid * 4);
        float4 vx = *(const float4*)(Wx + gid * 4);
        __half2* da = (__half2*)g_wa16 + gid * 2;
        __half2* dx = (__half2*)g_wx16 + gid * 2;
        da[0] = __floats2half2_rn(va.x, va.y);
        da[1] = __floats2half2_rn(va.z, va.w);
        dx[0] = __floats2half2_rn(vx.x, vx.y);
        dx[1] = __floats2half2_rn(vx.z, vx.w);
    }
}

// ---------- single fused kernel: hybrid dual GEMM + gates + full scan ----------
__global__ __launch_bounds__(256, 1)
void gemm_scan(const float* __restrict__ ba, const float* __restrict__ bx,
               const float* __restrict__ lmbd, float* __restrict__ out)
{
    extern __shared__ char sm[];
    const uint32_t sb = smem_u32(sm);
    const int tid  = threadIdx.x;
    const int wid  = tid >> 5, lane = tid & 31;
    const int g = lane >> 2, tg = lane & 3;
    const int wm2 = wid >> 2;          // 0..1 -> tensor M offset 48
    const int wn4 = wid & 3;           // 0..3 -> N offset 32

    // ticket -> tile
    __shared__ int s_ticket;
    if (tid == 0) s_ticket = atomicAdd(&g_sync[0], 1);
    __syncthreads();
    const int tk = s_ticket;
    const int nx = tk & 7;
    const int y  = tk >> 3;
    const int m0 = y * BM;
    const int n0 = nx * BN;

    float* s_ba = (float*)(sm + SM_BIAS);
    float* s_bx = s_ba + BN;
    float* s_la = s_bx + BN;
    for (int i = tid; i < BN; i += 256) {
        s_ba[i] = ba[n0 + i];
        s_bx[i] = bx[n0 + i];
        s_la[i] = -log1pf(expf(-lmbd[n0 + i]));   // log(sigmoid(lmbd))
    }

    const __half* xb  = g_x16  + (size_t)m0 * KK;
    const __half* wab = g_wa16 + (size_t)n0 * KK;
    const __half* wxb = g_wx16 + (size_t)n0 * KK;

    auto load_stage = [&](int s, int kc) {
        const uint32_t bA = sb + SM_STAGE + s * STAGE_BYTES;
        const int ko = kc * BK;
        #pragma unroll
        for (int i = 0; i < 4; i++) {
            int seg = tid + i * 256;
            int r = seg >> 3, c = seg & 7;
            uint32_t so = SWZ((uint32_t)(r * 128 + c * 16));
            size_t  go = (size_t)r * KK + ko + c * 8;
            cpa16(bA                 + so, xb  + go);
            cpa16(bA + ARR_BYTES     + so, wab + go);
            cpa16(bA + 2 * ARR_BYTES + so, wxb + go);
        }
    };

    // tensor accumulators: rows 0..95 (3 mt tiles of 16 per wm2 half of 48)
    float accA[3][4][4];
    float accX[3][4][4];
    #pragma unroll
    for (int a = 0; a < 3; a++)
        #pragma unroll
        for (int b = 0; b < 4; b++)
            #pragma unroll
            for (int c = 0; c < 4; c++) { accA[a][b][c] = 0.f; accX[a][b][c] = 0.f; }

    // SIMT (HFMA2) accumulators: rows 96..127
    // thread -> rows {r0l, r0l+1}, cols {c0 + 16j}
    const int r0l = 96 + 2 * (tid >> 4);
    const int c0  = tid & 15;
    __half2 hA[2][8], hX[2][8];
    float   sA[2][8], sX[2][8];
    #pragma unroll
    for (int r = 0; r < 2; r++)
        #pragma unroll
        for (int j = 0; j < 8; j++) { sA[r][j] = 0.f; sX[r][j] = 0.f; }

    load_stage(0, 0);
    asm volatile("cp.async.commit_group;" ::: "memory");
    load_stage(1, 1);
    asm volatile("cp.async.commit_group;" ::: "memory");

    const int rowA_l = (lane & 15);
    const int segA_l = ((lane >> 4) & 1) * 16;
    const int rowB_l = ((lane >> 4) << 3) + (lane & 7);
    const int segB_l = ((lane >> 3) & 1) * 16;

    for (int kc = 0; kc < NKC; kc++) {
        if (kc + 2 < NKC) load_stage((kc + 2) % PIPE, kc + 2);
        asm volatile("cp.async.commit_group;" ::: "memory");
        asm volatile("cp.async.wait_group 2;" ::: "memory");
        __syncthreads();

        const uint32_t bA  = sb + SM_STAGE + (kc % PIPE) * STAGE_BYTES;
        const uint32_t bWa = bA + ARR_BYTES;
        const uint32_t bWx = bA + 2 * ARR_BYTES;
        const char* pA  = sm + SM_STAGE + (kc % PIPE) * STAGE_BYTES;
        const char* pWa = pA + ARR_BYTES;
        const char* pWx = pA + 2 * ARR_BYTES;

        // zero fp16 working accumulators for this 64-k chunk
        #pragma unroll
        for (int r = 0; r < 2; r++)
            #pragma unroll
            for (int j = 0; j < 8; j++) {
                hA[r][j] = __float2half2_rn(0.f);
                hX[r][j] = __float2half2_rn(0.f);
            }

        // ---- tensor part: rows 0..95 ----
        #pragma unroll
        for (int kk = 0; kk < 4; kk++) {
            const int kb = kk * 32;
            uint32_t af[3][4];
            #pragma unroll
            for (int mt = 0; mt < 3; mt++) {
                int row = wm2 * 48 + mt * 16 + rowA_l;
                ldmx4(af[mt], bA + SWZ((uint32_t)(row * 128 + kb + segA_l)));
            }
            uint32_t bfa[4][2], bfx[4][2];
            #pragma unroll
            for (int p = 0; p < 2; p++) {
                int row = wn4 * 32 + p * 16 + rowB_l;
                uint32_t so = SWZ((uint32_t)(row * 128 + kb + segB_l));
                uint32_t t[4];
                ldmx4(t, bWa + so);
                bfa[2*p][0] = t[0]; bfa[2*p][1] = t[1];
                bfa[2*p+1][0] = t[2]; bfa[2*p+1][1] = t[3];
                ldmx4(t, bWx + so);
                bfx[2*p][0] = t[0]; bfx[2*p][1] = t[1];
                bfx[2*p+1][0] = t[2]; bfx[2*p+1][1] = t[3];
            }
            #pragma unroll
            for (int mt = 0; mt < 3; mt++)
                #pragma unroll
                for (int nt = 0; nt < 4; nt++) {
                    mma_f16(accA[mt][nt], af[mt], bfa[nt]);
                    mma_f16(accX[mt][nt], af[mt], bfx[nt]);
                }

            // ---- SIMT part interleaved: 16 k-elems (8 half2 steps) on fma pipe ----
            #pragma unroll
            for (int k2 = kk * 8; k2 < kk * 8 + 8; k2++) {
                __half2 a0 = *(const __half2*)(pA + SWZ((uint32_t)( r0l      * 128 + k2 * 4)));
                __half2 a1 = *(const __half2*)(pA + SWZ((uint32_t)((r0l + 1) * 128 + k2 * 4)));
                #pragma unroll
                for (int j = 0; j < 8; j++) {
                    uint32_t ob = SWZ((uint32_t)((c0 + 16 * j) * 128 + k2 * 4));
                    __half2 bva = *(const __half2*)(pWa + ob);
                    __half2 bvx = *(const __half2*)(pWx + ob);
                    hA[0][j] = __hfma2(a0, bva, hA[0][j]);
                    hA[1][j] = __hfma2(a1, bva, hA[1][j]);
                    hX[0][j] = __hfma2(a0, bvx, hX[0][j]);
                    hX[1][j] = __hfma2(a1, bvx, hX[1][j]);
                }
            }
        }

        // fold fp16 chunk partials into fp32 masters (bounds accumulation error)
        #pragma unroll
        for (int r = 0; r < 2; r++)
            #pragma unroll
            for (int j = 0; j < 8; j++) {
                float2 fa = __half22float2(hA[r][j]);
                float2 fx = __half22float2(hX[r][j]);
                sA[r][j] += fa.x + fa.y;
                sX[r][j] += fx.x + fx.y;
            }
        __syncthreads();
    }

    // ---- SMEM region for scan (overlaps stage buffers) ----
    float* s_at  = (float*)(sm + SM_STAGE);
    float* s_gg  = s_at + 128 * 129;
    float* s_pc  = s_gg + 128 * 129;
    float* s_hc  = s_pc + 512;
    float* s_hin = s_hc + 512;
    float* s_lb0 = s_hin + 512;
    float* s_lbP = s_lb0 + 128;
    float* s_lbH = s_lbP + 128;

    // gates -> SMEM: tensor rows 0..95
    #pragma unroll
    for (int mt = 0; mt < 3; mt++) {
        #pragma unroll
        for (int nt = 0; nt < 4; nt++) {
            #pragma unroll
            for (int cc = 0; cc < 2; cc++) {
                int nl = wn4 * 32 + nt * 8 + 2 * tg + cc;
                float la = s_la[nl], ban = s_ba[nl], bxn = s_bx[nl];
                #pragma unroll
                for (int half = 0; half < 2; half++) {
                    int ml = wm2 * 48 + mt * 16 + g + half * 8;
                    float za = accA[mt][nt][half * 2 + cc] + ban;
                    float zx = accX[mt][nt][half * 2 + cc] + bxn;
                    float rr = 1.f / (1.f + expf(-za));
                    float ii = 1.f / (1.f + expf(-zx));
                    float at = expf(8.f * rr * la);
                    s_at[ml * 129 + nl] = at;
                    s_gg[ml * 129 + nl] = sqrtf(fmaxf(0.f, 1.f - at * at)) * ii;
                }
            }
        }
    }
    // gates -> SMEM: SIMT rows 96..127
    #pragma unroll
    for (int r = 0; r < 2; r++) {
        int ml = r0l + r;
        #pragma unroll
        for (int j = 0; j < 8; j++) {
            int nl = c0 + 16 * j;
            float za = sA[r][j] + s_ba[nl];
            float zx = sX[r][j] + s_bx[nl];
            float rr = 1.f / (1.f + expf(-za));
            float ii = 1.f / (1.f + expf(-zx));
            float at = expf(8.f * rr * s_la[nl]);
            s_at[ml * 129 + nl] = at;
            s_gg[ml * 129 + nl] = sqrtf(fmaxf(0.f, 1.f - at * at)) * ii;
        }
    }
    __syncthreads();

    // ---- chunk pass: bt from fp16 x; convert rows in place to prefix form ----
    #pragma unroll
    for (int rep = 0; rep < 2; rep++) {
        int id  = tid + rep * 256;
        int ck  = id >> 7, col = id & 127;
        const __half* xr = g_x16 + (size_t)(m0 + ck * 32) * KK + n0 + col;
        float p = 1.f, h = 0.f;
        #pragma unroll 8
        for (int r = 0; r < 32; r++) {
            int off = (ck * 32 + r) * 129 + col;
            float at = s_at[off];
            float bt = s_gg[off] * __half2float(xr[(size_t)r * KK]);
            h = fmaf(at, h, bt);
            p *= at;
            s_at[off] = p;
            s_gg[off] = h;
        }
        s_pc[ck * 128 + col] = p;
        s_hc[ck * 128 + col] = h;
    }
    __syncthreads();

    // ---- publish block aggregates (BEFORE lookback) ----
    if (tid < 128) {
        float carry = 0.f, P = 1.f;
        #pragma unroll
        for (int c = 0; c < 4; c++) {
            carry = fmaf(s_pc[c * 128 + tid], carry, s_hc[c * 128 + tid]);
            P *= s_pc[c * 128 + tid];
        }
        g_Pc[y * DD + n0 + tid] = P;
        g_Hc[y * DD + n0 + tid] = carry;
    }
    __syncthreads();
    if (tid == 0) {
        __threadfence();
        st_release(&g_sync[16 + tk], 1);
    }

    // ---- decoupled lookback, split across two half-thread groups ----
    {
        int col  = tid & 127, half = tid >> 7;
        int yb   = y & ~(YPB - 1);
        int len  = y - yb;
        int jmid = yb + (len >> 1);
        if (half == 0) {
            float c = 0.f;
            for (int j = yb; j < jmid; j++) {
                int* fp = &g_sync[16 + j * 8 + nx];
                while (ld_acquire(fp) == 0) { }
                float Pj = __ldcg(&g_Pc[j * DD + n0 + col]);
                float Hj = __ldcg(&g_Hc[j * DD + n0 + col]);
                c = fmaf(Pj, c, Hj);
            }
            s_lb0[col] = c;
        } else {
            float P1 = 1.f, H1 = 0.f;
            for (int j = jmid; j < y; j++) {
                int* fp = &g_sync[16 + j * 8 + nx];
                while (ld_acquire(fp) == 0) { }
                float Pj = __ldcg(&g_Pc[j * DD + n0 + col]);
                float Hj = __ldcg(&g_Hc[j * DD + n0 + col]);
                H1 = fmaf(Pj, H1, Hj);
                P1 *= Pj;
            }
            s_lbP[col] = P1;
            s_lbH[col] = H1;
        }
    }
    __syncthreads();

    if (tid < 128) {
        float carry = fmaf(s_lbP[tid], s_lb0[tid], s_lbH[tid]);
        s_hin[tid] = carry;
        #pragma unroll
        for (int c = 0; c < 3; c++) {
            carry = fmaf(s_pc[c * 128 + tid], carry, s_hc[c * 128 + tid]);
            s_hin[(c + 1) * 128 + tid] = carry;
        }
    }
    __syncthreads();

    // ---- replay: fully parallel ----
    #pragma unroll
    for (int rep = 0; rep < 2; rep++) {
        int id  = tid + rep * 256;
        int ck  = id >> 7, col = id & 127;
        float* orow = out + (size_t)(m0 + ck * 32) * DD + n0 + col;
        float hin = s_hin[ck * 128 + col];
        #pragma unroll 8
        for (int r = 0; r < 32; r++) {
            int off = (ck * 32 + r) * 129 + col;
            orow[(size_t)r * DD] = fmaf(s_at[off], hin, s_gg[off]);
        }
    }
}

extern "C" void kernel_launch(void* const* d_in, const int* in_sizes, int n_in,
                              void* d_out, int out_size)
{
    (void)in_sizes; (void)n_in; (void)out_size;
    const float* x    = (const float*)d_in[0];
    const float* Wa   = (const float*)d_in[1];
    const float* Wx   = (const float*)d_in[2];
    const float* ba   = (const float*)d_in[3];
    const float* bx   = (const float*)d_in[4];
    const float* lmbd = (const float*)d_in[5];
    float* out = (float*)d_out;

    static int smem_set = 0;
    if (!smem_set) {
        cudaFuncSetAttribute(gemm_scan, cudaFuncAttributeMaxDynamicSharedMemorySize, SMEM_TOTAL);
        smem_set = 1;
    }

    void* sp = nullptr;
    cudaGetSymbolAddress(&sp, g_sync);
    cudaMemsetAsync(sp, 0, sizeof(int) * (16 + NYB * 8));

    convert_f16<<<((size_t)MM * KK / 4) / 256, 256>>>(x, Wa, Wx);
    gemm_scan<<<NYB * 8, 256, SMEM_TOTAL>>>(ba, bx, lmbd, out);
}

// round 14
// speedup vs baseline: 2.3996x; 2.3996x over previous
#include <cuda_runtime.h>
#include <cuda_fp16.h>
#include <cstdint>
#include <cstddef>

// Problem constants
#define BB 4
#define LL 4096
#define DD 1024
#define MM (BB * LL)      // 16384
#define KK 1024

// GEMM tiling (fp16 mma m16n8k16, f32 acc). 512 threads = 4 warps/SMSP
// experiment against the HMMA dispatch floor.
#define BM 128
#define BN 128            // per gate
#define BK 64             // k-chunk in halves = 128B per row
#define NKC (KK / BK)     // 16
#define PIPE 3

#define ARR_BYTES 16384                    // 128 rows x 128B
#define STAGE_BYTES (3 * ARR_BYTES)        // 49152
#define SM_BIAS  64
#define SM_STAGE 4096
#define SMEM_TOTAL (SM_STAGE + PIPE * STAGE_BYTES)  // 151552 B

#define SWZ(o) ((o) ^ (((o) >> 3) & 0x70))

#define NYB 128           // m-blocks (128 rows each); 32 per batch
#define YPB 32            // m-blocks per batch

// Scratch (allocation-free rule: __device__ globals)
__device__ __half g_x16 [(size_t)MM * KK];
__device__ __half g_wa16[(size_t)DD * KK];
__device__ __half g_wx16[(size_t)DD * KK];
__device__ float  g_Pc[NYB * DD];
__device__ float  g_Hc[NYB * DD];
__device__ int    g_sync[16 + NYB * 8];  // [0]=ticket, [16+tk]=publish flag

// ---------- helpers ----------
__device__ __forceinline__ uint32_t smem_u32(const void* p) {
    uint32_t a;
    asm("{ .reg .u64 t; cvta.to.shared.u64 t, %1; cvt.u32.u64 %0, t; }" : "=r"(a) : "l"(p));
    return a;
}

__device__ __forceinline__ void cpa16(uint32_t dst, const void* src) {
    asm volatile("cp.async.cg.shared.global [%0], [%1], 16;" :: "r"(dst), "l"(src));
}

__device__ __forceinline__ void ldmx4(uint32_t r[4], uint32_t addr) {
    asm volatile("ldmatrix.sync.aligned.m8n8.x4.shared.b16 {%0,%1,%2,%3}, [%4];"
                 : "=r"(r[0]), "=r"(r[1]), "=r"(r[2]), "=r"(r[3]) : "r"(addr));
}

__device__ __forceinline__ void mma_f16(float c[4], const uint32_t a[4], const uint32_t b[2]) {
    asm volatile(
        "mma.sync.aligned.m16n8k16.row.col.f32.f16.f16.f32 "
        "{%0,%1,%2,%3}, {%4,%5,%6,%7}, {%8,%9}, {%0,%1,%2,%3};"
        : "+f"(c[0]), "+f"(c[1]), "+f"(c[2]), "+f"(c[3])
        : "r"(a[0]), "r"(a[1]), "r"(a[2]), "r"(a[3]), "r"(b[0]), "r"(b[1]));
}

__device__ __forceinline__ void st_release(int* p, int v) {
    asm volatile("st.release.gpu.global.s32 [%0], %1;" :: "l"(p), "r"(v) : "memory");
}
__device__ __forceinline__ int ld_acquire(int* p) {
    int v;
    asm volatile("ld.acquire.gpu.global.s32 %0, [%1];" : "=r"(v) : "l"(p) : "memory");
    return v;
}

// ---------- fp32 -> fp16 pre-convert ----------
__global__ __launch_bounds__(256) void convert_f16(
    const float* __restrict__ x, const float* __restrict__ Wa, const float* __restrict__ Wx)
{
    size_t gid = (size_t)blockIdx.x * 256 + threadIdx.x;
    {
        float4 v = *(const float4*)(x + gid * 4);
        __half2* d = (__half2*)g_x16 + gid * 2;
        d[0] = __floats2half2_rn(v.x, v.y);
        d[1] = __floats2half2_rn(v.z, v.w);
    }
    if (gid < (size_t)(DD * KK) / 4) {
        float4 va = *(const float4*)(Wa + gid * 4);
        float4 vx = *(const float4*)(Wx + gid * 4);
        __half2* da = (__half2*)g_wa16 + gid * 2;
        __half2* dx = (__half2*)g_wx16 + gid * 2;
        da[0] = __floats2half2_rn(va.x, va.y);
        da[1] = __floats2half2_rn(va.z, va.w);
        dx[0] = __floats2half2_rn(vx.x, vx.y);
        dx[1] = __floats2half2_rn(vx.z, vx.w);
    }
}

// ---------- single fused kernel: dual GEMM + gates + full scan ----------
__global__ __launch_bounds__(512, 1)
void gemm_scan(const float* __restrict__ ba, const float* __restrict__ bx,
               const float* __restrict__ lmbd, float* __restrict__ out)
{
    extern __shared__ char sm[];
    const uint32_t sb = smem_u32(sm);
    const int tid  = threadIdx.x;
    const int wid  = tid >> 5, lane = tid & 31;
    const int g = lane >> 2, tg = lane & 3;
    const int wm4 = wid >> 2;          // 0..3 -> M offset 32
    const int wn4 = wid & 3;           // 0..3 -> N offset 32

    // ticket -> tile (predecessor m-blocks are resident or retired)
    __shared__ int s_ticket;
    if (tid == 0) s_ticket = atomicAdd(&g_sync[0], 1);
    __syncthreads();
    const int tk = s_ticket;
    const int nx = tk & 7;
    const int y  = tk >> 3;
    const int m0 = y * BM;
    const int n0 = nx * BN;

    float* s_ba = (float*)(sm + SM_BIAS);
    float* s_bx = s_ba + BN;
    float* s_la = s_bx + BN;
    for (int i = tid; i < BN; i += 512) {
        s_ba[i] = ba[n0 + i];
        s_bx[i] = bx[n0 + i];
        s_la[i] = -log1pf(expf(-lmbd[n0 + i]));   // log(sigmoid(lmbd))
    }

    const __half* xb  = g_x16  + (size_t)m0 * KK;
    const __half* wab = g_wa16 + (size_t)n0 * KK;
    const __half* wxb = g_wx16 + (size_t)n0 * KK;

    auto load_stage = [&](int s, int kc) {
        const uint32_t bA = sb + SM_STAGE + s * STAGE_BYTES;
        const int ko = kc * BK;
        #pragma unroll
        for (int i = 0; i < 2; i++) {
            int seg = tid + i * 512;
            int r = seg >> 3, c = seg & 7;
            uint32_t so = SWZ((uint32_t)(r * 128 + c * 16));
            size_t  go = (size_t)r * KK + ko + c * 8;
            cpa16(bA                 + so, xb  + go);
            cpa16(bA + ARR_BYTES     + so, wab + go);
            cpa16(bA + 2 * ARR_BYTES + so, wxb + go);
        }
    };

    float accA[2][4][4];
    float accX[2][4][4];
    #pragma unroll
    for (int a = 0; a < 2; a++)
        #pragma unroll
        for (int b = 0; b < 4; b++)
            #pragma unroll
            for (int c = 0; c < 4; c++) { accA[a][b][c] = 0.f; accX[a][b][c] = 0.f; }

    load_stage(0, 0);
    asm volatile("cp.async.commit_group;" ::: "memory");
    load_stage(1, 1);
    asm volatile("cp.async.commit_group;" ::: "memory");

    const int rowA_l = (lane & 15);
    const int segA_l = ((lane >> 4) & 1) * 16;
    const int rowB_l = ((lane >> 4) << 3) + (lane & 7);
    const int segB_l = ((lane >> 3) & 1) * 16;

    for (int kc = 0; kc < NKC; kc++) {
        if (kc + 2 < NKC) load_stage((kc + 2) % PIPE, kc + 2);
        asm volatile("cp.async.commit_group;" ::: "memory");
        asm volatile("cp.async.wait_group 2;" ::: "memory");
        __syncthreads();

        const uint32_t bA  = sb + SM_STAGE + (kc % PIPE) * STAGE_BYTES;
        const uint32_t bWa = bA + ARR_BYTES;
        const uint32_t bWx = bA + 2 * ARR_BYTES;

        #pragma unroll
        for (int kk = 0; kk < 4; kk++) {
            const int kb = kk * 32;
            uint32_t af[2][4];
            #pragma unroll
            for (int mt = 0; mt < 2; mt++) {
                int row = wm4 * 32 + mt * 16 + rowA_l;
                ldmx4(af[mt], bA + SWZ((uint32_t)(row * 128 + kb + segA_l)));
            }
            uint32_t bfa[4][2], bfx[4][2];
            #pragma unroll
            for (int p = 0; p < 2; p++) {
                int row = wn4 * 32 + p * 16 + rowB_l;
                uint32_t so = SWZ((uint32_t)(row * 128 + kb + segB_l));
                uint32_t t[4];
                ldmx4(t, bWa + so);
                bfa[2*p][0] = t[0]; bfa[2*p][1] = t[1];
                bfa[2*p+1][0] = t[2]; bfa[2*p+1][1] = t[3];
                ldmx4(t, bWx + so);
                bfx[2*p][0] = t[0]; bfx[2*p][1] = t[1];
                bfx[2*p+1][0] = t[2]; bfx[2*p+1][1] = t[3];
            }
            #pragma unroll
            for (int mt = 0; mt < 2; mt++)
                #pragma unroll
                for (int nt = 0; nt < 4; nt++) {
                    mma_f16(accA[mt][nt], af[mt], bfa[nt]);
                    mma_f16(accX[mt][nt], af[mt], bfx[nt]);
                }
        }
        __syncthreads();
    }

    // ---- SMEM region for scan (overlaps stage buffers) ----
    float* s_at  = (float*)(sm + SM_STAGE);     // a_t -> later: chunk prefix prod
    float* s_gg  = s_at + 128 * 129;            // sqrt(1-a^2)*i -> later: local prefix h
    float* s_pc  = s_gg + 128 * 129;            // [4][128] chunk prod
    float* s_hc  = s_pc + 512;                  // [4][128] chunk local h
    float* s_hin = s_hc + 512;                  // [4][128] chunk incoming h
    float* s_lb0 = s_hin + 512;                 // [128] lookback half-0 fold
    float* s_lbP = s_lb0 + 128;                 // [128] lookback half-1 P
    float* s_lbH = s_lbP + 128;                 // [128] lookback half-1 H

    // gates -> SMEM
    #pragma unroll
    for (int mt = 0; mt < 2; mt++) {
        #pragma unroll
        for (int nt = 0; nt < 4; nt++) {
            #pragma unroll
            for (int cc = 0; cc < 2; cc++) {
                int nl = wn4 * 32 + nt * 8 + 2 * tg + cc;
                float la = s_la[nl], ban = s_ba[nl], bxn = s_bx[nl];
                #pragma unroll
                for (int half = 0; half < 2; half++) {
                    int ml = wm4 * 32 + mt * 16 + g + half * 8;
                    float za = accA[mt][nt][half * 2 + cc] + ban;
                    float zx = accX[mt][nt][half * 2 + cc] + bxn;
                    float rr = 1.f / (1.f + expf(-za));
                    float ii = 1.f / (1.f + expf(-zx));
                    float at = expf(8.f * rr * la);
                    s_at[ml * 129 + nl] = at;
                    s_gg[ml * 129 + nl] = sqrtf(fmaxf(0.f, 1.f - at * at)) * ii;
                }
            }
        }
    }
    __syncthreads();

    // ---- chunk pass: bt from fp16 x; convert rows IN PLACE to prefix form ----
    {
        int ck  = tid >> 7, col = tid & 127;     // 512 threads = 4 chunks x 128 cols
        const __half* xr = g_x16 + (size_t)(m0 + ck * 32) * KK + n0 + col;
        float p = 1.f, h = 0.f;
        #pragma unroll 8
        for (int r = 0; r < 32; r++) {
            int off = (ck * 32 + r) * 129 + col;
            float at = s_at[off];
            float bt = s_gg[off] * __half2float(xr[(size_t)r * KK]);
            h = fmaf(at, h, bt);
            p *= at;
            s_at[off] = p;
            s_gg[off] = h;
        }
        s_pc[ck * 128 + col] = p;
        s_hc[ck * 128 + col] = h;
    }
    __syncthreads();

    // ---- publish block aggregates (BEFORE lookback) ----
    if (tid < 128) {
        float carry = 0.f, P = 1.f;
        #pragma unroll
        for (int c = 0; c < 4; c++) {
            carry = fmaf(s_pc[c * 128 + tid], carry, s_hc[c * 128 + tid]);
            P *= s_pc[c * 128 + tid];
        }
        g_Pc[y * DD + n0 + tid] = P;
        g_Hc[y * DD + n0 + tid] = carry;
    }
    __syncthreads();
    if (tid == 0) {
        __threadfence();
        st_release(&g_sync[16 + tk], 1);
    }

    // ---- decoupled lookback, split across two half-thread groups ----
    if (tid < 256) {
        int col  = tid & 127, half = tid >> 7;
        int yb   = y & ~(YPB - 1);
        int len  = y - yb;
        int jmid = yb + (len >> 1);
        if (half == 0) {
            float c = 0.f;
            for (int j = yb; j < jmid; j++) {
                int* fp = &g_sync[16 + j * 8 + nx];
                while (ld_acquire(fp) == 0) { }
                float Pj = __ldcg(&g_Pc[j * DD + n0 + col]);
                float Hj = __ldcg(&g_Hc[j * DD + n0 + col]);
                c = fmaf(Pj, c, Hj);
            }
            s_lb0[col] = c;
        } else {
            float P1 = 1.f, H1 = 0.f;
            for (int j = jmid; j < y; j++) {
                int* fp = &g_sync[16 + j * 8 + nx];
                while (ld_acquire(fp) == 0) { }
                float Pj = __ldcg(&g_Pc[j * DD + n0 + col]);
                float Hj = __ldcg(&g_Hc[j * DD + n0 + col]);
                H1 = fmaf(Pj, H1, Hj);
                P1 *= Pj;
            }
            s_lbP[col] = P1;
            s_lbH[col] = H1;
        }
    }
    __syncthreads();

    if (tid < 128) {
        float carry = fmaf(s_lbP[tid], s_lb0[tid], s_lbH[tid]);  // block incoming h
        s_hin[tid] = carry;
        #pragma unroll
        for (int c = 0; c < 3; c++) {
            carry = fmaf(s_pc[c * 128 + tid], carry, s_hc[c * 128 + tid]);
            s_hin[(c + 1) * 128 + tid] = carry;
        }
    }
    __syncthreads();

    // ---- replay: fully parallel (no serial chain, no global reads) ----
    {
        int ck  = tid >> 7, col = tid & 127;
        float* orow = out + (size_t)(m0 + ck * 32) * DD + n0 + col;
        float hin = s_hin[ck * 128 + col];
        #pragma unroll 8
        for (int r = 0; r < 32; r++) {
            int off = (ck * 32 + r) * 129 + col;
            orow[(size_t)r * DD] = fmaf(s_at[off], hin, s_gg[off]);
        }
    }
}

extern "C" void kernel_launch(void* const* d_in, const int* in_sizes, int n_in,
                              void* d_out, int out_size)
{
    (void)in_sizes; (void)n_in; (void)out_size;
    const float* x    = (const float*)d_in[0];
    const float* Wa   = (const float*)d_in[1];
    const float* Wx   = (const float*)d_in[2];
    const float* ba   = (const float*)d_in[3];
    const float* bx   = (const float*)d_in[4];
    const float* lmbd = (const float*)d_in[5];
    float* out = (float*)d_out;

    static int smem_set = 0;
    if (!smem_set) {
        cudaFuncSetAttribute(gemm_scan, cudaFuncAttributeMaxDynamicSharedMemorySize, SMEM_TOTAL);
        smem_set = 1;
    }

    void* sp = nullptr;
    cudaGetSymbolAddress(&sp, g_sync);
    cudaMemsetAsync(sp, 0, sizeof(int) * (16 + NYB * 8));

    convert_f16<<<((size_t)MM * KK / 4) / 256, 256>>>(x, Wa, Wx);
    gemm_scan<<<NYB * 8, 512, SMEM_TOTAL>>>(ba, bx, lmbd, out);
}